// round 5
// baseline (speedup 1.0000x reference)
#include <cuda_runtime.h>
#include <math.h>

// Geometry: x (2,1,160,160,16), q/lambda (2,3,160,160,16), f32, C-order.
#define PP 2
#define XD 160
#define YD 160
#define LPB (XD*YD)
#define NV (PP*LPB*4)        // float4 count in x-shaped array = 204800
#define T_ITERS 48
#define TX 16
#define TY 8
#define NBX (XD/TX)          // 10
#define NBY (YD/TY)          // 20
#define NBLK (PP*NBX*NBY)    // 400
#define NTHR (TX*TY*4)       // 512
#define QS 32767.0f

// Only xbar crosses blocks -> double-buffered global. Everything else resident.
__device__ float4 g_xbg[2][NV];
__device__ unsigned int g_ctr;
__device__ unsigned int g_flag;

__global__ void kreset() { g_ctr = 0u; g_flag = 0u; }

__device__ __forceinline__ float shfl_quad(float v, int lane, int delta4) {
    int src = (lane & ~3) | ((lane + delta4) & 3);
    return __shfl_sync(0xffffffffu, v, src);
}
__device__ __forceinline__ int shfl_quad_i(int v, int lane, int delta4) {
    int src = (lane & ~3) | ((lane + delta4) & 3);
    return __shfl_sync(0xffffffffu, v, src);
}
__device__ __forceinline__ float4 f4sub(float4 a, float4 b) {
    return make_float4(a.x-b.x, a.y-b.y, a.z-b.z, a.w-b.w);
}

struct I4 { int a, b, c, d; };
__device__ __forceinline__ I4 unpk(uint2 u) {
    I4 r;
    r.a = ((int)(u.x << 16)) >> 16;
    r.b = ((int)u.x) >> 16;
    r.c = ((int)(u.y << 16)) >> 16;
    r.d = ((int)u.y) >> 16;
    return r;
}
__device__ __forceinline__ uint2 pk(I4 v) {
    uint2 u;
    u.x = ((unsigned)v.a & 0xffffu) | ((unsigned)v.b << 16);
    u.y = ((unsigned)v.c & 0xffffu) | ((unsigned)v.d << 16);
    return u;
}
// Q' = clamp(round(Q + ss*g), -L, L) in int16 units. Deterministic: identical
// inputs give identical results on owner and halo-tracker threads.
__device__ __forceinline__ I4 qstep_i(uint2 q, uint2 l, float4 g, float ss) {
    I4 qi = unpk(q), li = unpk(l), r;
    r.a = max(-li.a, min(__float2int_rn(fmaf(ss, g.x, (float)qi.a)), li.a));
    r.b = max(-li.b, min(__float2int_rn(fmaf(ss, g.y, (float)qi.b)), li.b));
    r.c = max(-li.c, min(__float2int_rn(fmaf(ss, g.z, (float)qi.c)), li.c));
    r.d = max(-li.d, min(__float2int_rn(fmaf(ss, g.w, (float)qi.d)), li.d));
    return r;
}
__device__ __forceinline__ uint2 lam2pk(float4 l) {
    I4 li;
    li.a = __float2int_rn(l.x * QS);
    li.b = __float2int_rn(l.y * QS);
    li.c = __float2int_rn(l.z * QS);
    li.d = __float2int_rn(l.w * QS);
    return pk(li);
}

// Software grid barrier (all 400 blocks co-resident by construction).
__device__ __forceinline__ void gbar(unsigned int gen) {
    __syncthreads();
    if (threadIdx.x == 0) {
        __threadfence();
        unsigned int old = atomicAdd(&g_ctr, 1u);
        if (old == gen * NBLK - 1u) {
            atomicExch(&g_flag, gen);
        } else {
            volatile unsigned int* vf = &g_flag;
            while (*vf < gen) { }
        }
        __threadfence();
    }
    __syncthreads();
}

__global__ void __launch_bounds__(NTHR, 3) kpersist(
    const float4* __restrict__ xn, const float4* __restrict__ lam,
    float4* __restrict__ out,
    float sigma, float sigma_s, float inv1ps, float tau, float tau_s, float theta)
{
    __shared__ float4 sxb[TX][TY][4];        // xbar tile (current iter)
    __shared__ float4 sxn[NTHR];             // noisy input (constant)
    __shared__ uint2  slam[3*NTHR];          // lambda int16 (constant)
    __shared__ uint2  sq0[TX+1][TY][4];      // Q0' with left halo at [0]
    __shared__ uint2  sq1[TX][TY+1][4];      // Q1' with top halo at [0]

    int bid = blockIdx.x;
    int pp  = bid / (NBX*NBY);
    int t   = bid % (NBX*NBY);
    int bx  = t / NBY, by = t % NBY;
    int x0g = bx*TX, y0g = by*TY;

    int tid  = threadIdx.x;
    int quad = tid & 3;
    int ll   = tid >> 2;           // 0..127
    int lx   = ll >> 3;            // 0..15
    int ly   = ll & 7;             // 0..7
    int lane = tid & 31;

    int base   = pp * LPB;
    int gx = x0g + lx, gy = y0g + ly;
    int line2d = gx*YD + gy;
    int gid    = (base + line2d)*4 + quad;

    // Out-of-tile +1 neighbor global indices (used only by edge threads).
    int xti = (base + ((x0g+TX) % XD)*YD + gy)*4 + quad;
    int yti = (base + gx*YD + ((y0g+TY) % YD))*4 + quad;

    // ---- prologue: load everything once ----
    float4 v   = xn[gid];
    float4 pv  = v, x0v = v, xbv = v;
    sxn[tid] = v;
    #pragma unroll
    for (int d = 0; d < 3; d++)
        slam[d*NTHR + tid] = lam2pk(lam[((pp*3+d)*LPB + line2d)*4 + quad]);

    uint2 Q0 = make_uint2(0u,0u), Q1 = make_uint2(0u,0u), Q2 = make_uint2(0u,0u);

    sxb[lx][ly][quad] = v;
    g_xbg[0][gid] = v;

    // ---- halo-tracker roles (threads 0..95) ----
    int    hgid = 0;
    uint2  hQ = make_uint2(0u,0u), hL = make_uint2(0u,0u);
    float4* hsrc = 0;
    uint2*  hdst = 0;
    if (tid < 32) {                      // Q0 halo line (x0g-1, y0g+h)
        int h   = tid >> 2;
        int hx  = (x0g == 0) ? XD-1 : x0g-1;
        int h2d = hx*YD + (y0g + h);
        hgid = (base + h2d)*4 + quad;
        hL   = lam2pk(lam[((pp*3+0)*LPB + h2d)*4 + quad]);
        hsrc = &sxb[0][h][quad];
        hdst = &sq0[0][h][quad];
    } else if (tid < 96) {               // Q1 halo line (x0g+h, y0g-1)
        int h   = (tid - 32) >> 2;
        int hy  = (y0g == 0) ? YD-1 : y0g-1;
        int h2d = (x0g + h)*YD + hy;
        hgid = (base + h2d)*4 + quad;
        hL   = lam2pk(lam[((pp*3+1)*LPB + h2d)*4 + quad]);
        hsrc = &sxb[h][0][quad];
        hdst = &sq1[h][0][quad];
    }

    unsigned int gen = 1u;
    gbar(gen); gen++;                    // xbar_0 globally visible

    for (int k = 0; k < T_ITERS; k++) {
        const float4* __restrict__ gin = g_xbg[k & 1];

        // xbar +1 neighbors: smem inside tile, global across tile edges
        float4 xbx = (lx == TX-1) ? gin[xti] : sxb[lx+1][ly][quad];
        float4 xby = (ly == TY-1) ? gin[yti] : sxb[lx][ly+1][quad];

        float nxt = shfl_quad(xbv.x, lane, 1);
        float4 gtv = make_float4(xbv.y-xbv.x, xbv.z-xbv.y, xbv.w-xbv.z, nxt-xbv.w);
        float4 gxv = f4sub(xbx, xbv);
        float4 gyv = f4sub(xby, xbv);

        uint2 L0 = slam[tid], L1 = slam[NTHR+tid], L2 = slam[2*NTHR+tid];
        I4 q0 = qstep_i(Q0, L0, gxv, sigma_s); Q0 = pk(q0); sq0[lx+1][ly][quad] = Q0;
        I4 q1 = qstep_i(Q1, L1, gyv, sigma_s); Q1 = pk(q1); sq1[lx][ly+1][quad] = Q1;
        I4 q2 = qstep_i(Q2, L2, gtv, sigma_s); Q2 = pk(q2);

        // halo Q tracked locally; publish into smem for adj
        if (tid < 96) {
            float4 a = gin[hgid];
            float4 b = *hsrc;
            I4 hq = qstep_i(hQ, hL, f4sub(b, a), sigma_s);
            hQ = pk(hq);
            *hdst = hQ;
        }

        // p update (registers only)
        float4 xnv = sxn[tid];
        pv.x = (pv.x + sigma*(xbv.x - xnv.x)) * inv1ps;
        pv.y = (pv.y + sigma*(xbv.y - xnv.y)) * inv1ps;
        pv.z = (pv.z + sigma*(xbv.z - xnv.z)) * inv1ps;
        pv.w = (pv.w + sigma*(xbv.w - xnv.w)) * inv1ps;

        __syncthreads();

        I4 q0m = unpk(sq0[lx][ly][quad]);
        I4 q1m = unpk(sq1[lx][ly][quad]);
        int prevw = shfl_quad_i(q2.d, lane, -1);

        int adja = (q0m.a - q0.a) + (q1m.a - q1.a) + (prevw - q2.a);
        int adjb = (q0m.b - q0.b) + (q1m.b - q1.b) + (q2.a  - q2.b);
        int adjc = (q0m.c - q0.c) + (q1m.c - q1.c) + (q2.b  - q2.c);
        int adjd = (q0m.d - q0.d) + (q1m.d - q1.d) + (q2.c  - q2.d);

        float4 x1;
        x1.x = x0v.x - tau*pv.x - tau_s*__int2float_rn(adja);
        x1.y = x0v.y - tau*pv.y - tau_s*__int2float_rn(adjb);
        x1.z = x0v.z - tau*pv.z - tau_s*__int2float_rn(adjc);
        x1.w = x0v.w - tau*pv.w - tau_s*__int2float_rn(adjd);

        float opt = 1.0f + theta;
        float4 xbn;
        xbn.x = opt*x1.x - theta*x0v.x;
        xbn.y = opt*x1.y - theta*x0v.y;
        xbn.z = opt*x1.z - theta*x0v.z;
        xbn.w = opt*x1.w - theta*x0v.w;

        x0v = x1;
        xbv = xbn;

        if (k < T_ITERS-1) {
            g_xbg[(k+1) & 1][gid] = xbv;   // publish for edge/halo consumers
            sxb[lx][ly][quad]     = xbv;   // in-tile consumers
            gbar(gen); gen++;
        }
    }

    out[gid] = x0v;                        // x1 after 48 iterations
}

extern "C" void kernel_launch(void* const* d_in, const int* in_sizes, int n_in,
                              void* d_out, int out_size) {
    const float4* x   = (const float4*)d_in[0];
    const float4* lam = (const float4*)d_in[1];
    float4* out = (float4*)d_out;

    // Let occupancy use full shared memory (3 blocks x 37KB per SM). Hint only;
    // idempotent, safe under capture.
    cudaFuncSetAttribute(kpersist, cudaFuncAttributePreferredSharedMemoryCarveout, 100);

    float L     = sqrtf(13.0f);
    float s10   = 1.0f / (1.0f + expf(-10.0f));
    float sigma = s10 / L;
    float tau   = s10 / L;
    float theta = s10;
    float inv1ps  = 1.0f / (1.0f + sigma);
    float sigma_s = sigma * QS;
    float tau_s   = tau / QS;

    kreset<<<1, 1>>>();
    kpersist<<<NBLK, NTHR>>>(x, lam, out, sigma, sigma_s, inv1ps, tau, tau_s, theta);
}

// round 6
// speedup vs baseline: 1.2474x; 1.2474x over previous
#include <cuda_runtime.h>
#include <math.h>

// Geometry: x (2,1,160,160,16), q/lambda (2,3,160,160,16), f32, C-order.
#define PP 2
#define XD 160
#define YD 160
#define LPB (XD*YD)
#define NV (PP*LPB*4)        // float4 count in x-shaped array = 204800
#define T_ITERS 48
#define TX 16
#define TY 8
#define NBX (XD/TX)          // 10
#define NBY (YD/TY)          // 20
#define NBLK (PP*NBX*NBY)    // 400
#define NTHR (TX*TY*4)       // 512
#define QS 32767.0f
#define FPAD 32              // flag padding (u32s) -> one 128B line per flag

// Only boundary xbar crosses blocks -> double-buffered global (edges only used).
__device__ float4 g_xbg[2][NV];
__device__ unsigned int g_flags[NBLK*FPAD];

__global__ void kreset() {
    int i = blockIdx.x*blockDim.x + threadIdx.x;
    if (i < NBLK) g_flags[i*FPAD] = 0u;
}

__device__ __forceinline__ unsigned int ld_acq(const unsigned int* p) {
    unsigned int v;
    asm volatile("ld.acquire.gpu.global.u32 %0, [%1];" : "=r"(v) : "l"(p) : "memory");
    return v;
}
__device__ __forceinline__ void st_rel(unsigned int* p, unsigned int v) {
    asm volatile("st.release.gpu.global.u32 [%0], %1;" :: "l"(p), "r"(v) : "memory");
}

__device__ __forceinline__ float shfl_quad(float v, int lane, int delta4) {
    int src = (lane & ~3) | ((lane + delta4) & 3);
    return __shfl_sync(0xffffffffu, v, src);
}
__device__ __forceinline__ int shfl_quad_i(int v, int lane, int delta4) {
    int src = (lane & ~3) | ((lane + delta4) & 3);
    return __shfl_sync(0xffffffffu, v, src);
}
__device__ __forceinline__ float4 f4sub(float4 a, float4 b) {
    return make_float4(a.x-b.x, a.y-b.y, a.z-b.z, a.w-b.w);
}

struct I4 { int a, b, c, d; };
__device__ __forceinline__ I4 unpk(uint2 u) {
    I4 r;
    r.a = ((int)(u.x << 16)) >> 16;
    r.b = ((int)u.x) >> 16;
    r.c = ((int)(u.y << 16)) >> 16;
    r.d = ((int)u.y) >> 16;
    return r;
}
__device__ __forceinline__ uint2 pk(I4 v) {
    uint2 u;
    u.x = ((unsigned)v.a & 0xffffu) | ((unsigned)v.b << 16);
    u.y = ((unsigned)v.c & 0xffffu) | ((unsigned)v.d << 16);
    return u;
}
// Q' = clamp(round(Q + ss*g), -L, L) in int16 units. Deterministic: identical
// inputs give identical results on owner and halo-tracker threads.
__device__ __forceinline__ I4 qstep_i(uint2 q, uint2 l, float4 g, float ss) {
    I4 qi = unpk(q), li = unpk(l), r;
    r.a = max(-li.a, min(__float2int_rn(fmaf(ss, g.x, (float)qi.a)), li.a));
    r.b = max(-li.b, min(__float2int_rn(fmaf(ss, g.y, (float)qi.b)), li.b));
    r.c = max(-li.c, min(__float2int_rn(fmaf(ss, g.z, (float)qi.c)), li.c));
    r.d = max(-li.d, min(__float2int_rn(fmaf(ss, g.w, (float)qi.d)), li.d));
    return r;
}
__device__ __forceinline__ uint2 lam2pk(float4 l) {
    I4 li;
    li.a = __float2int_rn(l.x * QS);
    li.b = __float2int_rn(l.y * QS);
    li.c = __float2int_rn(l.z * QS);
    li.d = __float2int_rn(l.w * QS);
    return pk(li);
}

__global__ void __launch_bounds__(NTHR, 3) kpersist(
    const float4* __restrict__ xn, const float4* __restrict__ lam,
    float4* __restrict__ out,
    float sigma, float sigma_s, float inv1ps, float tau, float tau_s, float theta)
{
    __shared__ float4 sxb[TX][TY][4];        // xbar tile (current gen)
    __shared__ float4 sxn[NTHR];             // noisy input (constant)
    __shared__ uint2  slam[3*NTHR];          // lambda int16 (constant)
    __shared__ uint2  sq0[TX+1][TY][4];      // Q0' with left halo at [0]
    __shared__ uint2  sq1[TX][TY+1][4];      // Q1' with top halo at [0]

    int bid = blockIdx.x;
    int pp  = bid / (NBX*NBY);
    int t   = bid % (NBX*NBY);
    int bx  = t / NBY, by = t % NBY;
    int x0g = bx*TX, y0g = by*TY;

    int tid  = threadIdx.x;
    int quad = tid & 3;
    int ll   = tid >> 2;           // 0..127
    int lx   = ll >> 3;            // 0..15
    int ly   = ll & 7;             // 0..7
    int lane = tid & 31;

    int base   = pp * LPB;
    int gx = x0g + lx, gy = y0g + ly;
    int line2d = gx*YD + gy;
    int gid    = (base + line2d)*4 + quad;

    // Out-of-tile +1 neighbor global indices (used only by edge threads).
    int xti = (base + ((x0g+TX) % XD)*YD + gy)*4 + quad;
    int yti = (base + gx*YD + ((y0g+TY) % YD))*4 + quad;

    // Lattice neighbors whose flags gate this block (also = my consumers).
    int bxm = (bx == 0) ? NBX-1 : bx-1;
    int bxp = (bx == NBX-1) ? 0 : bx+1;
    int bym = (by == 0) ? NBY-1 : by-1;
    int byp = (by == NBY-1) ? 0 : by+1;
    int nb0 = (pp*NBX + bxm)*NBY + by;
    int nb1 = (pp*NBX + bxp)*NBY + by;
    int nb2 = (pp*NBX + bx )*NBY + bym;
    int nb3 = (pp*NBX + bx )*NBY + byp;
    const unsigned int* nflag = 0;
    if      (tid == 0) nflag = &g_flags[nb0*FPAD];
    else if (tid == 1) nflag = &g_flags[nb1*FPAD];
    else if (tid == 2) nflag = &g_flags[nb2*FPAD];
    else if (tid == 3) nflag = &g_flags[nb3*FPAD];
    unsigned int* myflag = &g_flags[bid*FPAD];

    // Sites neighbors actually read: 2 boundary rows + 2 boundary cols.
    bool pub = (lx == 0) | (lx == TX-1) | (ly == 0) | (ly == TY-1);

    // ---- prologue: load everything once ----
    float4 v   = xn[gid];
    float4 pv  = v, x0v = v, xbv = v;
    sxn[tid] = v;
    #pragma unroll
    for (int d = 0; d < 3; d++)
        slam[d*NTHR + tid] = lam2pk(lam[((pp*3+d)*LPB + line2d)*4 + quad]);

    uint2 Q0 = make_uint2(0u,0u), Q1 = make_uint2(0u,0u), Q2 = make_uint2(0u,0u);

    sxb[lx][ly][quad] = v;
    if (pub) g_xbg[0][gid] = v;

    // ---- halo-tracker roles (threads 0..95) ----
    int    hgid = 0;
    uint2  hQ = make_uint2(0u,0u), hL = make_uint2(0u,0u);
    float4* hsrc = 0;
    uint2*  hdst = 0;
    if (tid < 32) {                      // Q0 halo line (x0g-1, y0g+h)
        int h   = tid >> 2;
        int hx  = (x0g == 0) ? XD-1 : x0g-1;
        int h2d = hx*YD + (y0g + h);
        hgid = (base + h2d)*4 + quad;
        hL   = lam2pk(lam[((pp*3+0)*LPB + h2d)*4 + quad]);
        hsrc = &sxb[0][h][quad];
        hdst = &sq0[0][h][quad];
    } else if (tid < 96) {               // Q1 halo line (x0g+h, y0g-1)
        int h   = (tid - 32) >> 2;
        int hy  = (y0g == 0) ? YD-1 : y0g-1;
        int h2d = (x0g + h)*YD + hy;
        hgid = (base + h2d)*4 + quad;
        hL   = lam2pk(lam[((pp*3+1)*LPB + h2d)*4 + quad]);
        hsrc = &sxb[h][0][quad];
        hdst = &sq1[h][0][quad];
    }

    __syncthreads();                     // all boundary stores done
    if (tid == 0) st_rel(myflag, 1u);    // xbar gen 0 published

    for (int k = 0; k < T_ITERS; k++) {
        // Wait: 4 neighbors have published gen k (also implies they finished
        // reading gen k-1 from the buffer we are about to overwrite).
        unsigned int want = (unsigned int)(k + 1);
        if (nflag) { while (ld_acq(nflag) < want) { } }
        __syncthreads();

        const float4* gin = g_xbg[k & 1];

        // xbar +1 neighbors: smem inside tile, L2 (.cv, L1-bypass) across edges
        float4 xbx = (lx == TX-1) ? __ldcv(gin + xti) : sxb[lx+1][ly][quad];
        float4 xby = (ly == TY-1) ? __ldcv(gin + yti) : sxb[lx][ly+1][quad];

        float nxt = shfl_quad(xbv.x, lane, 1);
        float4 gtv = make_float4(xbv.y-xbv.x, xbv.z-xbv.y, xbv.w-xbv.z, nxt-xbv.w);
        float4 gxv = f4sub(xbx, xbv);
        float4 gyv = f4sub(xby, xbv);

        uint2 L0 = slam[tid], L1 = slam[NTHR+tid], L2 = slam[2*NTHR+tid];
        I4 q0 = qstep_i(Q0, L0, gxv, sigma_s); Q0 = pk(q0); sq0[lx+1][ly][quad] = Q0;
        I4 q1 = qstep_i(Q1, L1, gyv, sigma_s); Q1 = pk(q1); sq1[lx][ly+1][quad] = Q1;
        I4 q2 = qstep_i(Q2, L2, gtv, sigma_s); Q2 = pk(q2);

        // halo Q tracked locally (bitwise = neighbor's owner value)
        if (tid < 96) {
            float4 a = __ldcv(gin + hgid);
            float4 b = *hsrc;
            I4 hq = qstep_i(hQ, hL, f4sub(b, a), sigma_s);
            hQ = pk(hq);
            *hdst = hQ;
        }

        // p update (registers only)
        float4 xnv = sxn[tid];
        pv.x = (pv.x + sigma*(xbv.x - xnv.x)) * inv1ps;
        pv.y = (pv.y + sigma*(xbv.y - xnv.y)) * inv1ps;
        pv.z = (pv.z + sigma*(xbv.z - xnv.z)) * inv1ps;
        pv.w = (pv.w + sigma*(xbv.w - xnv.w)) * inv1ps;

        __syncthreads();

        I4 q0m = unpk(sq0[lx][ly][quad]);
        I4 q1m = unpk(sq1[lx][ly][quad]);
        int prevw = shfl_quad_i(q2.d, lane, -1);

        int adja = (q0m.a - q0.a) + (q1m.a - q1.a) + (prevw - q2.a);
        int adjb = (q0m.b - q0.b) + (q1m.b - q1.b) + (q2.a  - q2.b);
        int adjc = (q0m.c - q0.c) + (q1m.c - q1.c) + (q2.b  - q2.c);
        int adjd = (q0m.d - q0.d) + (q1m.d - q1.d) + (q2.c  - q2.d);

        float4 x1;
        x1.x = x0v.x - tau*pv.x - tau_s*__int2float_rn(adja);
        x1.y = x0v.y - tau*pv.y - tau_s*__int2float_rn(adjb);
        x1.z = x0v.z - tau*pv.z - tau_s*__int2float_rn(adjc);
        x1.w = x0v.w - tau*pv.w - tau_s*__int2float_rn(adjd);

        float opt = 1.0f + theta;
        float4 xbn;
        xbn.x = opt*x1.x - theta*x0v.x;
        xbn.y = opt*x1.y - theta*x0v.y;
        xbn.z = opt*x1.z - theta*x0v.z;
        xbn.w = opt*x1.w - theta*x0v.w;

        x0v = x1;
        xbv = xbn;

        if (k < T_ITERS-1) {
            if (pub) g_xbg[(k+1) & 1][gid] = xbv;   // boundary only
            sxb[lx][ly][quad] = xbv;
            __syncthreads();                         // block's stores complete
            if (tid == 0) st_rel(myflag, (unsigned int)(k + 2));
        }
    }

    out[gid] = x0v;                        // x1 after 48 iterations
}

extern "C" void kernel_launch(void* const* d_in, const int* in_sizes, int n_in,
                              void* d_out, int out_size) {
    const float4* x   = (const float4*)d_in[0];
    const float4* lam = (const float4*)d_in[1];
    float4* out = (float4*)d_out;

    cudaFuncSetAttribute(kpersist, cudaFuncAttributePreferredSharedMemoryCarveout, 100);

    float L     = sqrtf(13.0f);
    float s10   = 1.0f / (1.0f + expf(-10.0f));
    float sigma = s10 / L;
    float tau   = s10 / L;
    float theta = s10;
    float inv1ps  = 1.0f / (1.0f + sigma);
    float sigma_s = sigma * QS;
    float tau_s   = tau / QS;

    kreset<<<1, NBLK>>>();
    kpersist<<<NBLK, NTHR>>>(x, lam, out, sigma, sigma_s, inv1ps, tau, tau_s, theta);
}

// round 8
// speedup vs baseline: 1.2494x; 1.0016x over previous
#include <cuda_runtime.h>
#include <math.h>

// Geometry: x (2,1,160,160,16), q/lambda (2,3,160,160,16), f32, C-order.
#define PP 2
#define XD 160
#define YD 160
#define LPB (XD*YD)
#define NV (PP*LPB*4)        // float4 count in x-shaped array = 204800
#define T_ITERS 48
#define TX 16
#define TY 8
#define NBX (XD/TX)          // 10
#define NBY (YD/TY)          // 20
#define NBLK (PP*NBX*NBY)    // 400
#define NTHR (TX*TY*4)       // 512
#define QS 32767.0f
#define FPAD 32              // one 128B line per flag

// Only boundary xbar crosses blocks -> double-buffered global (edges only used).
__device__ float4 g_xbg[2][NV];
__device__ unsigned int g_flags[NBLK*FPAD];

__global__ void kreset() {
    int i = blockIdx.x*blockDim.x + threadIdx.x;
    if (i < NBLK) g_flags[i*FPAD] = 0u;
}

__device__ __forceinline__ unsigned int ld_acq(const unsigned int* p) {
    unsigned int v;
    asm volatile("ld.acquire.gpu.global.u32 %0, [%1];" : "=r"(v) : "l"(p) : "memory");
    return v;
}
__device__ __forceinline__ void st_rel(unsigned int* p, unsigned int v) {
    asm volatile("st.release.gpu.global.u32 [%0], %1;" :: "l"(p), "r"(v) : "memory");
}

__device__ __forceinline__ float shfl_quad(float v, int lane, int delta4) {
    int src = (lane & ~3) | ((lane + delta4) & 3);
    return __shfl_sync(0xffffffffu, v, src);
}
__device__ __forceinline__ int shfl_quad_i(int v, int lane, int delta4) {
    int src = (lane & ~3) | ((lane + delta4) & 3);
    return __shfl_sync(0xffffffffu, v, src);
}
__device__ __forceinline__ float4 f4sub(float4 a, float4 b) {
    return make_float4(a.x-b.x, a.y-b.y, a.z-b.z, a.w-b.w);
}

struct I4 { int a, b, c, d; };
__device__ __forceinline__ I4 unpk(uint2 u) {
    I4 r;
    r.a = ((int)(u.x << 16)) >> 16;
    r.b = ((int)u.x) >> 16;
    r.c = ((int)(u.y << 16)) >> 16;
    r.d = ((int)u.y) >> 16;
    return r;
}
__device__ __forceinline__ uint2 lam2pk(float4 l) {
    int a = __float2int_rn(l.x * QS), b = __float2int_rn(l.y * QS);
    int c = __float2int_rn(l.z * QS), d = __float2int_rn(l.w * QS);
    uint2 u;
    u.x = ((unsigned)a & 0xffffu) | ((unsigned)b << 16);
    u.y = ((unsigned)c & 0xffffu) | ((unsigned)d << 16);
    return u;
}

// SIMD packed-s16 dual step: Q' = clamp(sat16(Q + sat16(rni(ss*g))), -L, +L).
// Pure packed ops: no unpack of Q or L. Deterministic (same code on owner and
// halo-tracker paths).
__device__ __forceinline__ uint2 qstep_p(uint2 Q, uint2 L, float4 g, float ss) {
    short d0, d1, d2, d3;
    asm("cvt.rni.sat.s16.f32 %0, %1;" : "=h"(d0) : "f"(ss * g.x));
    asm("cvt.rni.sat.s16.f32 %0, %1;" : "=h"(d1) : "f"(ss * g.y));
    asm("cvt.rni.sat.s16.f32 %0, %1;" : "=h"(d2) : "f"(ss * g.z));
    asm("cvt.rni.sat.s16.f32 %0, %1;" : "=h"(d3) : "f"(ss * g.w));
    unsigned int lo, hi;
    asm("mov.b32 %0, {%1,%2};" : "=r"(lo) : "h"(d0), "h"(d1));
    asm("mov.b32 %0, {%1,%2};" : "=r"(hi) : "h"(d2), "h"(d3));
    uint2 r;
    r.x = __vmaxs2(__vmins2(__vaddss2(Q.x, lo), L.x), __vsubss2(0u, L.x));
    r.y = __vmaxs2(__vmins2(__vaddss2(Q.y, hi), L.y), __vsubss2(0u, L.y));
    return r;
}

__global__ void __launch_bounds__(NTHR, 3) kpersist(
    const float4* __restrict__ xn, const float4* __restrict__ lam,
    float4* __restrict__ out,
    float sigma, float sigma_s, float inv1ps, float tau, float tau_s, float theta)
{
    __shared__ float4 sxb[TX][TY][4];        // xbar tile (current gen)
    __shared__ float4 sxn[NTHR];             // noisy input (constant)
    __shared__ uint2  slam[3*NTHR];          // lambda int16 packed (constant)
    __shared__ uint2  sq0[TX+1][TY][4];      // Q0' with left halo at [0]
    __shared__ uint2  sq1h[TX][4];           // Q1 halo col only (y-dir uses shfl)

    int bid = blockIdx.x;
    int pp  = bid / (NBX*NBY);
    int t   = bid % (NBX*NBY);
    int bx  = t / NBY, by = t % NBY;
    int x0g = bx*TX, y0g = by*TY;

    int tid  = threadIdx.x;
    int quad = tid & 3;
    int ll   = tid >> 2;           // 0..127
    int lx   = ll >> 3;            // 0..15  (== warp index)
    int ly   = ll & 7;             // 0..7   (== lane>>2)
    int lane = tid & 31;

    int base   = pp * LPB;
    int gx = x0g + lx, gy = y0g + ly;
    int line2d = gx*YD + gy;
    int gid    = (base + line2d)*4 + quad;

    // Out-of-tile +1 neighbor global indices (edge threads only).
    int xti = (base + ((x0g+TX) % XD)*YD + gy)*4 + quad;
    int yti = (base + gx*YD + ((y0g+TY) % YD))*4 + quad;

    // Lattice neighbors whose flags gate this block.
    int bxm = (bx == 0) ? NBX-1 : bx-1;
    int bxp = (bx == NBX-1) ? 0 : bx+1;
    int bym = (by == 0) ? NBY-1 : by-1;
    int byp = (by == NBY-1) ? 0 : by+1;
    int nb0 = (pp*NBX + bxm)*NBY + by;
    int nb1 = (pp*NBX + bxp)*NBY + by;
    int nb2 = (pp*NBX + bx )*NBY + bym;
    int nb3 = (pp*NBX + bx )*NBY + byp;
    const unsigned int* nflag = 0;
    if      (tid == 0) nflag = &g_flags[nb0*FPAD];
    else if (tid == 1) nflag = &g_flags[nb1*FPAD];
    else if (tid == 2) nflag = &g_flags[nb2*FPAD];
    else if (tid == 3) nflag = &g_flags[nb3*FPAD];
    unsigned int* myflag = &g_flags[bid*FPAD];

    // Sites neighbors actually read: boundary rows/cols.
    bool pub = (lx == 0) | (lx == TX-1) | (ly == 0) | (ly == TY-1);

    // ---- prologue ----
    float4 v   = xn[gid];
    float4 pv  = v, x0v = v, xbv = v;
    sxn[tid] = v;
    #pragma unroll
    for (int d = 0; d < 3; d++)
        slam[d*NTHR + tid] = lam2pk(lam[((pp*3+d)*LPB + line2d)*4 + quad]);

    uint2 Q0 = make_uint2(0u,0u), Q1 = make_uint2(0u,0u), Q2 = make_uint2(0u,0u);

    sxb[lx][ly][quad] = v;
    if (pub) g_xbg[0][gid] = v;

    // ---- halo-tracker roles (threads 0..95) ----
    int    hgid = 0;
    uint2  hQ = make_uint2(0u,0u), hL = make_uint2(0u,0u);
    float4* hsrc = 0;
    uint2*  hdst = 0;
    if (tid < 32) {                      // Q0 halo line (x0g-1, y0g+h)
        int h   = tid >> 2;
        int hx  = (x0g == 0) ? XD-1 : x0g-1;
        int h2d = hx*YD + (y0g + h);
        hgid = (base + h2d)*4 + quad;
        hL   = lam2pk(lam[((pp*3+0)*LPB + h2d)*4 + quad]);
        hsrc = &sxb[0][h][quad];
        hdst = &sq0[0][h][quad];
    } else if (tid < 96) {               // Q1 halo line (x0g+h, y0g-1)
        int h   = (tid - 32) >> 2;
        int hy  = (y0g == 0) ? YD-1 : y0g-1;
        int h2d = (x0g + h)*YD + hy;
        hgid = (base + h2d)*4 + quad;
        hL   = lam2pk(lam[((pp*3+1)*LPB + h2d)*4 + quad]);
        hsrc = &sxb[h][0][quad];
        hdst = &sq1h[h][quad];
    }

    __syncthreads();
    if (tid == 0) st_rel(myflag, 1u);    // xbar gen 0 published

    for (int k = 0; k < T_ITERS; k++) {
        unsigned int want = (unsigned int)(k + 1);
        if (nflag) { while (ld_acq(nflag) < want) { } }
        __syncthreads();

        const float4* gin = g_xbg[k & 1];

        // +1 neighbors: smem in x, L2 across tile edges
        float4 xbx = (lx == TX-1) ? __ldcv(gin + xti) : sxb[lx+1][ly][quad];
        float4 xby = (ly == TY-1) ? __ldcv(gin + yti) : sxb[lx][ly+1][quad];

        float nxt = shfl_quad(xbv.x, lane, 1);
        float4 gtv = make_float4(xbv.y-xbv.x, xbv.z-xbv.y, xbv.w-xbv.z, nxt-xbv.w);
        float4 gxv = f4sub(xbx, xbv);
        float4 gyv = f4sub(xby, xbv);

        uint2 L0 = slam[tid], L1 = slam[NTHR+tid], L2 = slam[2*NTHR+tid];
        Q0 = qstep_p(Q0, L0, gxv, sigma_s); sq0[lx+1][ly][quad] = Q0;
        Q1 = qstep_p(Q1, L1, gyv, sigma_s);
        Q2 = qstep_p(Q2, L2, gtv, sigma_s);

        // halo Q tracked locally (bitwise = neighbor's owner value)
        if (tid < 96) {
            float4 a = __ldcv(gin + hgid);
            float4 b = *hsrc;
            hQ = qstep_p(hQ, hL, f4sub(b, a), sigma_s);
            *hdst = hQ;
        }

        // p update (registers only)
        float4 xnv = sxn[tid];
        pv.x = (pv.x + sigma*(xbv.x - xnv.x)) * inv1ps;
        pv.y = (pv.y + sigma*(xbv.y - xnv.y)) * inv1ps;
        pv.z = (pv.z + sigma*(xbv.z - xnv.z)) * inv1ps;
        pv.w = (pv.w + sigma*(xbv.w - xnv.w)) * inv1ps;

        // y-neighbor Q1 (ly-1) lives in lane-4 of the same warp
        uint2 Q1u;
        Q1u.x = __shfl_up_sync(0xffffffffu, Q1.x, 4);
        Q1u.y = __shfl_up_sync(0xffffffffu, Q1.y, 4);

        __syncthreads();

        uint2 q0mp = sq0[lx][ly][quad];
        uint2 q1mp = (ly == 0) ? sq1h[lx][quad] : Q1u;

        I4 q0  = unpk(Q0),   q1  = unpk(Q1),   q2 = unpk(Q2);
        I4 q0m = unpk(q0mp), q1m = unpk(q1mp);
        int prevw = shfl_quad_i(q2.d, lane, -1);

        int adja = (q0m.a - q0.a) + (q1m.a - q1.a) + (prevw - q2.a);
        int adjb = (q0m.b - q0.b) + (q1m.b - q1.b) + (q2.a  - q2.b);
        int adjc = (q0m.c - q0.c) + (q1m.c - q1.c) + (q2.b  - q2.c);
        int adjd = (q0m.d - q0.d) + (q1m.d - q1.d) + (q2.c  - q2.d);

        float4 x1;
        x1.x = x0v.x - tau*pv.x - tau_s*__int2float_rn(adja);
        x1.y = x0v.y - tau*pv.y - tau_s*__int2float_rn(adjb);
        x1.z = x0v.z - tau*pv.z - tau_s*__int2float_rn(adjc);
        x1.w = x0v.w - tau*pv.w - tau_s*__int2float_rn(adjd);

        float opt = 1.0f + theta;
        float4 xbn;
        xbn.x = opt*x1.x - theta*x0v.x;
        xbn.y = opt*x1.y - theta*x0v.y;
        xbn.z = opt*x1.z - theta*x0v.z;
        xbn.w = opt*x1.w - theta*x0v.w;

        x0v = x1;
        xbv = xbn;

        if (k < T_ITERS-1) {
            if (pub) g_xbg[(k+1) & 1][gid] = xbv;   // boundary only
            sxb[lx][ly][quad] = xbv;
            __syncthreads();
            if (tid == 0) st_rel(myflag, (unsigned int)(k + 2));
        }
    }

    out[gid] = x0v;                        // x1 after 48 iterations
}

extern "C" void kernel_launch(void* const* d_in, const int* in_sizes, int n_in,
                              void* d_out, int out_size) {
    const float4* x   = (const float4*)d_in[0];
    const float4* lam = (const float4*)d_in[1];
    float4* out = (float4*)d_out;

    cudaFuncSetAttribute(kpersist, cudaFuncAttributePreferredSharedMemoryCarveout, 100);

    float L     = sqrtf(13.0f);
    float s10   = 1.0f / (1.0f + expf(-10.0f));
    float sigma = s10 / L;
    float tau   = s10 / L;
    float theta = s10;
    float inv1ps  = 1.0f / (1.0f + sigma);
    float sigma_s = sigma * QS;
    float tau_s   = tau / QS;

    kreset<<<1, NBLK>>>();
    kpersist<<<NBLK, NTHR>>>(x, lam, out, sigma, sigma_s, inv1ps, tau, tau_s, theta);
}